// round 1
// baseline (speedup 1.0000x reference)
#include <cuda_runtime.h>

// Problem constants
#define NB 8
#define NC 21
#define NW 512
#define NH 512
#define KK 5
#define KPAD 2

// Block: 128 threads, each handles 4 contiguous h-pixels (float4) of one row w.
// Grid: (NW, NB).
__global__ __launch_bounds__(128, 8)
void weight_matrix_kernel(const float* __restrict__ x,
                          const int*   __restrict__ y,
                          float*       __restrict__ out)
{
    // y tile: rows w-2..w+2, columns -2..513 stored at index col+2 (0..515).
    // Row stride 520 ints = 2080 B (16B multiple) so &ytile[r][4*tid] is
    // 16B-aligned -> int4 shared loads are conflict-free.
    __shared__ int ytile[KK][520];

    const int w   = blockIdx.x;
    const int b   = blockIdx.y;
    const int tid = threadIdx.x;
    const int h0  = tid * 4;

    // ---- stage y neighborhood rows into smem (coalesced global reads) ----
    const int* yb = y + b * (NW * NH);
    for (int idx = tid; idx < KK * 516; idx += 128) {
        const int r  = idx / 516;          // 0..4
        const int cc = idx - r * 516;      // 0..515 (stored col)
        const int gr = w - KPAD + r;       // global row
        const int gc = cc - KPAD;          // global col
        int v = 0;                          // zero padding like nn.Unfold
        if (gr >= 0 && gr < NW && gc >= 0 && gc < NH)
            v = __ldg(&yb[gr * NH + gc]);
        ytile[r][cc] = v;
    }
    __syncthreads();

    // ---- argmax over 21 channels for 4 pixels (strict > => first max) ----
    const float* xb = x + ((b * NC) * NW + w) * NH + h0;   // channel 0
    float4 best = *reinterpret_cast<const float4*>(xb);
    int bc0 = 0, bc1 = 0, bc2 = 0, bc3 = 0;

    #pragma unroll 5
    for (int c = 1; c < NC; c++) {
        const float4 v = *reinterpret_cast<const float4*>(xb + c * (NW * NH));
        if (v.x > best.x) { best.x = v.x; bc0 = c; }
        if (v.y > best.y) { best.y = v.y; bc1 = c; }
        if (v.z > best.z) { best.z = v.z; bc2 = c; }
        if (v.w > best.w) { best.w = v.w; bc3 = c; }
    }

    // ---- 5x5 neighborhood mismatch count ----
    // pixel p (p=0..3) neighbor col h0+p+dj-2 -> stored index h0+p+dj.
    // Thread window = stored cols h0 .. h0+7 : two int4 loads per row.
    int cnt0 = 0, cnt1 = 0, cnt2 = 0, cnt3 = 0;

    #pragma unroll
    for (int di = 0; di < KK; di++) {
        const int4 lo = *reinterpret_cast<const int4*>(&ytile[di][h0]);
        const int4 hi = *reinterpret_cast<const int4*>(&ytile[di][h0 + 4]);
        const int a0 = lo.x, a1 = lo.y, a2 = lo.z, a3 = lo.w;
        const int a4 = hi.x, a5 = hi.y, a6 = hi.z, a7 = hi.w;

        cnt0 += (a0 != bc0) + (a1 != bc0) + (a2 != bc0) + (a3 != bc0) + (a4 != bc0);
        cnt1 += (a1 != bc1) + (a2 != bc1) + (a3 != bc1) + (a4 != bc1) + (a5 != bc1);
        cnt2 += (a2 != bc2) + (a3 != bc2) + (a4 != bc2) + (a5 != bc2) + (a6 != bc2);
        cnt3 += (a3 != bc3) + (a4 != bc3) + (a5 != bc3) + (a6 != bc3) + (a7 != bc3);
    }

    float4 o;
    o.x = 1.0f + 1.5f * (float)cnt0;
    o.y = 1.0f + 1.5f * (float)cnt1;
    o.z = 1.0f + 1.5f * (float)cnt2;
    o.w = 1.0f + 1.5f * (float)cnt3;

    *reinterpret_cast<float4*>(out + (b * NW + w) * NH + h0) = o;
}

extern "C" void kernel_launch(void* const* d_in, const int* in_sizes, int n_in,
                              void* d_out, int out_size)
{
    const float* x = (const float*)d_in[0];
    const int*   y = (const int*)d_in[1];
    float*       o = (float*)d_out;

    dim3 grid(NW, NB);
    weight_matrix_kernel<<<grid, 128>>>(x, y, o);
}